// round 3
// baseline (speedup 1.0000x reference)
#include <cuda_runtime.h>
#include <cuda_bf16.h>

// ---------------------------------------------------------------------------
// AdditiveAttention: B=4, LQ=LK=256, D=768
//   q = query@Wq + bq ; k = key@Wk + bk ; v = value@Wv + bv
//   scores[b,q,k] = sum_d Ws[d] * tanh(q[b,q,d] + k[b,k,d])   (+bs cancels in softmax)
//   weights = softmax_k(scores) ; attended = weights @ v
// Outputs: attended [4,256,768] then weights [4,256,256] (flattened, fp32)
// ---------------------------------------------------------------------------

#define B_ 4
#define L_ 256
#define D_ 768
#define M_ (B_ * L_)          // 1024 rows for projection GEMMs

// scratch (allocation-free rule: __device__ globals)
__device__ __align__(16) float g_qp[M_ * D_];
__device__ __align__(16) float g_kp[M_ * D_];
__device__ __align__(16) float g_vp[M_ * D_];
__device__ __align__(16) float g_w [B_ * L_ * L_];   // softmax weights

// ---------------------------------------------------------------------------
// Kernel 1: projection GEMM  Y[m,n] = sum_k X[m,k]*W[k,n] + bias[n]
// 128x128 tile, BK=8, 256 threads, 8x8 micro-tile, double-buffered smem.
// ---------------------------------------------------------------------------
__global__ __launch_bounds__(256, 1)
void proj_gemm_kernel(const float* __restrict__ Xq, const float* __restrict__ Xk,
                      const float* __restrict__ Xv,
                      const float* __restrict__ Wq, const float* __restrict__ bq,
                      const float* __restrict__ Wk, const float* __restrict__ bk,
                      const float* __restrict__ Wv, const float* __restrict__ bv)
{
    const int z = blockIdx.z;
    const float* X    = (z == 0) ? Xq : (z == 1) ? Xk : Xv;
    const float* W    = (z == 0) ? Wq : (z == 1) ? Wk : Wv;
    const float* bias = (z == 0) ? bq : (z == 1) ? bk : bv;
    float*       Y    = (z == 0) ? g_qp : (z == 1) ? g_kp : g_vp;

    __shared__ __align__(16) float As[2][8][128];
    __shared__ __align__(16) float Bs[2][8][128];

    const int tid = threadIdx.x;
    const int m0 = blockIdx.y * 128;
    const int n0 = blockIdx.x * 128;

    const int a_row = tid >> 1;
    const int a_col = (tid & 1) * 4;
    const int b_row = tid >> 5;
    const int b_col = (tid & 31) * 4;

    const float* Abase = X + (m0 + a_row) * D_ + a_col;
    const float* Bbase = W + b_row * D_ + n0 + b_col;

    const int NCHUNK = D_ / 8;   // 96

    float4 af = *(const float4*)(Abase);
    float4 bf = *(const float4*)(Bbase);

    int buf = 0;
    As[buf][a_col + 0][a_row] = af.x;
    As[buf][a_col + 1][a_row] = af.y;
    As[buf][a_col + 2][a_row] = af.z;
    As[buf][a_col + 3][a_row] = af.w;
    *(float4*)&Bs[buf][b_row][b_col] = bf;
    __syncthreads();

    const int tx = tid & 15;
    const int ty = tid >> 4;

    float acc[8][8];
    #pragma unroll
    for (int i = 0; i < 8; i++)
        #pragma unroll
        for (int j = 0; j < 8; j++) acc[i][j] = 0.f;

    for (int kt = 0; kt < NCHUNK; kt++) {
        float4 af_n, bf_n;
        if (kt + 1 < NCHUNK) {
            af_n = *(const float4*)(Abase + (kt + 1) * 8);
            bf_n = *(const float4*)(Bbase + (size_t)(kt + 1) * 8 * D_);
        }
        #pragma unroll
        for (int kk = 0; kk < 8; kk++) {
            float a_frag[8], b_frag[8];
            *(float4*)&a_frag[0] = *(const float4*)&As[buf][kk][ty * 8];
            *(float4*)&a_frag[4] = *(const float4*)&As[buf][kk][ty * 8 + 4];
            *(float4*)&b_frag[0] = *(const float4*)&Bs[buf][kk][tx * 8];
            *(float4*)&b_frag[4] = *(const float4*)&Bs[buf][kk][tx * 8 + 4];
            #pragma unroll
            for (int i = 0; i < 8; i++)
                #pragma unroll
                for (int j = 0; j < 8; j++)
                    acc[i][j] += a_frag[i] * b_frag[j];
        }
        if (kt + 1 < NCHUNK) {
            buf ^= 1;
            As[buf][a_col + 0][a_row] = af_n.x;
            As[buf][a_col + 1][a_row] = af_n.y;
            As[buf][a_col + 2][a_row] = af_n.z;
            As[buf][a_col + 3][a_row] = af_n.w;
            *(float4*)&Bs[buf][b_row][b_col] = bf_n;
            __syncthreads();
        }
    }

    float bv8[8];
    #pragma unroll
    for (int j = 0; j < 8; j++) bv8[j] = __ldg(bias + n0 + tx * 8 + j);

    #pragma unroll
    for (int i = 0; i < 8; i++) {
        float* yrow = Y + (size_t)(m0 + ty * 8 + i) * D_ + n0 + tx * 8;
        float4 o0, o1;
        o0.x = acc[i][0] + bv8[0]; o0.y = acc[i][1] + bv8[1];
        o0.z = acc[i][2] + bv8[2]; o0.w = acc[i][3] + bv8[3];
        o1.x = acc[i][4] + bv8[4]; o1.y = acc[i][5] + bv8[5];
        o1.z = acc[i][6] + bv8[6]; o1.w = acc[i][7] + bv8[7];
        *(float4*)(yrow)     = o0;
        *(float4*)(yrow + 4) = o1;
    }
}

// ---------------------------------------------------------------------------
// Kernel 2: scores (MUFU.TANH) + softmax -> weights (g_w and optionally out_w)
// TQ=2: grid = 512 CTAs of 256 threads, up to 4 CTAs/SM co-resident.
// Thread t owns key row t; q-pair & Ws broadcast from smem.
// ---------------------------------------------------------------------------
#define TQ 2

__device__ __forceinline__ float tanh_fast(float x) {
    float y;
    asm("tanh.approx.f32 %0, %1;" : "=f"(y) : "f"(x));
    return y;
}

__global__ __launch_bounds__(256, 4)
void scores_kernel(const float* __restrict__ Ws,
                   float* __restrict__ out_w)     // may be null
{
    __shared__ __align__(16) float sq[TQ][D_];     // 6 KB
    __shared__ __align__(16) float sws[D_];        // 3 KB
    __shared__ float ssc[TQ][L_];                  // 2 KB
    __shared__ float smax[TQ], sinv[TQ];

    const int tid = threadIdx.x;
    const int b  = blockIdx.x >> 7;                // 128 q-tiles per batch
    const int q0 = (blockIdx.x & 127) * TQ;

    const float4* qbase = (const float4*)(g_qp + (size_t)(b * L_ + q0) * D_);
    #pragma unroll
    for (int i = tid; i < TQ * D_ / 4; i += 256)
        ((float4*)&sq[0][0])[i] = qbase[i];
    for (int i = tid; i < D_ / 4; i += 256)
        ((float4*)sws)[i] = ((const float4*)Ws)[i];
    __syncthreads();

    // ---- scores: acc[q] = sum_d Ws[d]*tanh(q[q][d] + k[t][d]) ----
    const float4* kb4 = (const float4*)(g_kp + ((size_t)b * L_ + tid) * D_);
    float acc0 = 0.f, acc1 = 0.f;

    float4 c0 = kb4[0], c1 = kb4[1];   // current 8 k-values
    #pragma unroll 1
    for (int ch = 0; ch < D_ / 8; ch++) {
        float4 n0, n1;
        if (ch + 1 < D_ / 8) {         // prefetch next chunk (hides L2 latency)
            n0 = kb4[(ch + 1) * 2];
            n1 = kb4[(ch + 1) * 2 + 1];
        }
        const int d0 = ch * 8;
        float kr[8];
        *(float4*)&kr[0] = c0;
        *(float4*)&kr[4] = c1;
        #pragma unroll
        for (int dd = 0; dd < 8; dd++) {
            const float w  = sws[d0 + dd];
            const float kv = kr[dd];
            acc0 += w * tanh_fast(sq[0][d0 + dd] + kv);
            acc1 += w * tanh_fast(sq[1][d0 + dd] + kv);
        }
        c0 = n0; c1 = n1;
    }

    ssc[0][tid] = acc0;
    ssc[1][tid] = acc1;
    __syncthreads();

    // ---- softmax over k (warp w reduces row w) ----
    const int w = tid >> 5, lane = tid & 31;
    if (w < TQ) {
        float m = -1e30f;
        #pragma unroll
        for (int j = 0; j < 8; j++) m = fmaxf(m, ssc[w][lane + j * 32]);
        #pragma unroll
        for (int o = 16; o > 0; o >>= 1) m = fmaxf(m, __shfl_xor_sync(0xffffffffu, m, o));
        float s = 0.f;
        #pragma unroll
        for (int j = 0; j < 8; j++) s += __expf(ssc[w][lane + j * 32] - m);
        #pragma unroll
        for (int o = 16; o > 0; o >>= 1) s += __shfl_xor_sync(0xffffffffu, s, o);
        if (lane == 0) { smax[w] = m; sinv[w] = 1.0f / s; }
    }
    __syncthreads();

    const float wt0 = __expf(acc0 - smax[0]) * sinv[0];
    const float wt1 = __expf(acc1 - smax[1]) * sinv[1];

    float* gw = g_w + ((size_t)(b * L_ + q0)) * L_ + tid;
    gw[0]  = wt0;
    gw[L_] = wt1;
    if (out_w) {
        float* ow = out_w + ((size_t)(b * L_ + q0)) * L_ + tid;
        ow[0]  = wt0;
        ow[L_] = wt1;
    }
}

// ---------------------------------------------------------------------------
// Kernel 3: attended = weights @ v   (per batch: [256q x 256k] x [256k x 768d])
// Tile 64q x 128d, BK=32, 256 threads, micro-tile 8q x 4d.
// grid = (6 d-tiles, 4 q-tiles, 4 batches) = 96 CTAs.
// ---------------------------------------------------------------------------
__global__ __launch_bounds__(256, 2)
void av_kernel(float* __restrict__ out_att)
{
    __shared__ __align__(16) float w_s[32][64];    // [k][q]  8 KB
    __shared__ __align__(16) float v_s[32][128];   // [k][d] 16 KB

    const int tid = threadIdx.x;
    const int b  = blockIdx.z;
    const int q0 = blockIdx.y * 64;
    const int n0 = blockIdx.x * 128;

    const float* wbase = g_w  + ((size_t)(b * L_ + q0)) * L_;   // [64][256]
    const float* vbase = g_vp + (size_t)b * L_ * D_;            // [256][768]

    const int tx = tid & 31;   // d: 4 cols each
    const int ty = tid >> 5;   // q: 8 rows each

    float acc[8][4];
    #pragma unroll
    for (int i = 0; i < 8; i++)
        #pragma unroll
        for (int j = 0; j < 4; j++) acc[i][j] = 0.f;

    for (int k0 = 0; k0 < L_; k0 += 32) {
        // load w tile [64q x 32k] -> w_s[k][q] (transposed)
        {
            const int q = tid >> 2;            // 0..63
            const int kb = (tid & 3) * 8;      // 0,8,16,24
            const float4 wa = *(const float4*)(wbase + (size_t)q * L_ + k0 + kb);
            const float4 wb = *(const float4*)(wbase + (size_t)q * L_ + k0 + kb + 4);
            w_s[kb + 0][q] = wa.x; w_s[kb + 1][q] = wa.y;
            w_s[kb + 2][q] = wa.z; w_s[kb + 3][q] = wa.w;
            w_s[kb + 4][q] = wb.x; w_s[kb + 5][q] = wb.y;
            w_s[kb + 6][q] = wb.z; w_s[kb + 7][q] = wb.w;
        }
        // load v tile [32k x 128d]
        #pragma unroll
        for (int r = 0; r < 4; r++) {
            const int idx = tid + r * 256;         // float4 index, 1024 total
            const int kk = idx >> 5;               // /32 float4 per row
            const int dd = (idx & 31) * 4;
            *(float4*)&v_s[kk][dd] =
                *(const float4*)(vbase + (size_t)(k0 + kk) * D_ + n0 + dd);
        }
        __syncthreads();

        #pragma unroll
        for (int kk = 0; kk < 32; kk++) {
            float a_frag[8], b_frag[4];
            *(float4*)&a_frag[0] = *(const float4*)&w_s[kk][ty * 8];
            *(float4*)&a_frag[4] = *(const float4*)&w_s[kk][ty * 8 + 4];
            *(float4*)&b_frag[0] = *(const float4*)&v_s[kk][tx * 4];
            #pragma unroll
            for (int i = 0; i < 8; i++)
                #pragma unroll
                for (int j = 0; j < 4; j++)
                    acc[i][j] += a_frag[i] * b_frag[j];
        }
        __syncthreads();
    }

    #pragma unroll
    for (int i = 0; i < 8; i++) {
        float* o = out_att + ((size_t)(b * L_ + q0 + ty * 8 + i)) * D_ + n0 + tx * 4;
        float4 ov;
        ov.x = acc[i][0]; ov.y = acc[i][1]; ov.z = acc[i][2]; ov.w = acc[i][3];
        *(float4*)o = ov;
    }
}

// ---------------------------------------------------------------------------
extern "C" void kernel_launch(void* const* d_in, const int* in_sizes, int n_in,
                              void* d_out, int out_size)
{
    const float* query = (const float*)d_in[0];
    const float* key   = (const float*)d_in[1];
    const float* value = (const float*)d_in[2];
    const float* Wq    = (const float*)d_in[3];
    const float* bq    = (const float*)d_in[4];
    const float* Wk    = (const float*)d_in[5];
    const float* bk    = (const float*)d_in[6];
    const float* Wv    = (const float*)d_in[7];
    const float* bv    = (const float*)d_in[8];
    const float* Ws    = (const float*)d_in[9];
    // d_in[10] = bs: constant shift inside softmax -> cancels; unused.

    float* out = (float*)d_out;
    const int ATT_N = B_ * L_ * D_;   // 786432
    const int W_N   = B_ * L_ * L_;   // 262144

    float* out_att = nullptr;
    float* out_w   = nullptr;
    if (out_size >= ATT_N + W_N) {
        out_att = out;
        out_w   = out + ATT_N;
    } else if (out_size == ATT_N) {
        out_att = out;
    } else {
        out_w = out;
    }

    dim3 ggrid(D_ / 128, M_ / 128, 3);        // (6, 8, 3)
    proj_gemm_kernel<<<ggrid, 256>>>(query, key, value, Wq, bq, Wk, bk, Wv, bv);

    scores_kernel<<<B_ * (L_ / TQ), 256>>>(Ws, out_w);

    if (out_att) {
        dim3 agrid(D_ / 128, L_ / 64, B_);    // (6, 4, 4)
        av_kernel<<<agrid, 256>>>(out_att);
    }
}